// round 7
// baseline (speedup 1.0000x reference)
#include <cuda_runtime.h>
#include <cuda_bf16.h>

// Problem constants (fixed by the dataset): B=32, L=256, V=50000, C=128
#define CC   128
#define LL   256
#define BDIM 256

__global__ __launch_bounds__(BDIM, 1)
void crf_fwd_kernel(const int*   __restrict__ tokens,
                    const int*   __restrict__ target,
                    const float* __restrict__ mask,
                    const float* __restrict__ st,      // state_table [V, C]
                    const float* __restrict__ trans,   // trans_matrix [C, C]
                    float*       __restrict__ out)     // [B]
{
    // p (exp-domain partition vector), double buffered. 4-float pad between the
    // two 64-entry halves (offset 68) -> the two half-broadcast float4 reads hit
    // disjoint bank groups.
    __shared__ __align__(16) float p_s[2][136];
    __shared__ int   tok_s[LL];
    __shared__ float m_s[LL];
    __shared__ float red_s[8], red2_s[8];

    const int b    = blockIdx.x;
    const int tid  = threadIdx.x;
    const int w    = tid >> 5;
    const int l    = tid & 31;
    const int j    = w * 16 + (l & 15);   // state index 0..127 (owned by 2 lanes)
    const int half = l >> 4;              // which 64-wide half of i this lane sums

    // ---- stage tokens/mask + target-path energy partial ----
    tok_s[tid] = tokens[b * LL + tid];
    m_s[tid]   = mask[b * LL + tid];
    float tgt_part;
    {
        const int t    = tid;                                  // BDIM == LL
        const int tg   = target[b * LL + t];
        const int prev = (t == 0) ? (CC - 1) : target[b * LL + t - 1];
        const int tok  = tokens[b * LL + t];
        tgt_part = (trans[prev * CC + tg] + st[tok * CC + tg]) * mask[b * LL + t];
    }

    // ---- E[k] = exp(trans[half*64+k][j]) in registers ----
    float E[64];
#pragma unroll
    for (int k = 0; k < 64; ++k)
        E[k] = __expf(trans[(half * 64 + k) * CC + j]);

    __syncthreads();   // tok_s/m_s visible

    // ---- init: p_1[j] = exp((trans[C-1][j] + em_0[j]) * m0) ----
    const float m0 = m_s[0];
    const int   sj = j + ((j >> 6) << 2);   // padded store index
    float p = __expf((trans[(CC - 1) * CC + j] + st[tok_s[0] * CC + j]) * m0);
    if (half == 0) p_s[0][sj] = p;

    // emission pipeline: ec = exp(em_t) for current step, en = raw em_{t+1}
    float ec = __expf(st[tok_s[1] * CC + j]);
    float en = st[tok_s[2] * CC + j];

    float S = 0.0f;    // accumulated shift; true part[j] = log p[j] + S
    __syncthreads();

    // ---- sequential scan: pure exp-domain matvec, 1 bar/step, no MUFU on path ----
    for (int t = 1; t < LL; ++t) {
        const int   rb = (t - 1) & 1, wb = t & 1;
        const float p0 = p_s[rb][0];               // normalization source (broadcast)
        const float mt = m_s[t];

        // prefetch raw emission row for step t+2 (off critical path)
        float emr = 0.0f;
        if (t + 2 < LL) emr = __ldg(&st[tok_s[t + 2] * CC + j]);

        // matvec: s_half = sum_k p[half*64+k] * E[k]
        const float* ap = &p_s[rb][half * 68];
        float s0 = 0.f, s1 = 0.f, s2 = 0.f, s3 = 0.f;
#pragma unroll
        for (int k = 0; k < 64; k += 4) {
            const float4 av = *reinterpret_cast<const float4*>(ap + k);
            s0 = fmaf(av.x, E[k + 0], s0);
            s1 = fmaf(av.y, E[k + 1], s1);
            s2 = fmaf(av.z, E[k + 2], s2);
            s3 = fmaf(av.w, E[k + 3], s3);
        }
        float s = (s0 + s1) + (s2 + s3);
        s += __shfl_xor_sync(0xffffffffu, s, 16);  // combine the two halves

        if (mt != 0.0f) {                          // uniform branch (mask is scalar/step)
            const float inv = __fdividef(1.0f, p0);   // MUFU.RCP, overlapped w/ matvec
            p = s * ec * inv;
            if (tid == 0) S += __logf(p0);            // off-path, thread 0 only
        }
        // mt == 0: p (and S) unchanged — exact CRF mask semantics for m in {0,1}

        if (half == 0) p_s[wb][sj] = p;

        ec = __expf(en);                           // exp for step t+1, off-path
        en = emr;
        __syncthreads();
    }

    // ---- epilogue: loss = S + log(sum_j p[j]) - tgt_energy ----
    float c = (half == 0) ? p : 0.0f;              // each state counted once
#pragma unroll
    for (int o = 16; o; o >>= 1) c += __shfl_xor_sync(0xffffffffu, c, o);
    float tp = tgt_part;
#pragma unroll
    for (int o = 16; o; o >>= 1) tp += __shfl_xor_sync(0xffffffffu, tp, o);
    if (l == 0) { red_s[w] = c; red2_s[w] = tp; }
    __syncthreads();

    if (tid == 0) {
        float ss = 0.f, ts = 0.f;
#pragma unroll
        for (int i = 0; i < 8; ++i) { ss += red_s[i]; ts += red2_s[i]; }
        out[b] = S + logf(ss) - ts;
    }
}

extern "C" void kernel_launch(void* const* d_in, const int* in_sizes, int n_in,
                              void* d_out, int out_size)
{
    const int*   tokens = (const int*)  d_in[0];
    const int*   target = (const int*)  d_in[1];
    const float* mask   = (const float*)d_in[2];
    const float* st     = (const float*)d_in[3];
    const float* trans  = (const float*)d_in[4];
    float*       out    = (float*)d_out;

    const int B = in_sizes[0] / LL;   // 32
    crf_fwd_kernel<<<B, BDIM>>>(tokens, target, mask, st, trans, out);
}

// round 8
// speedup vs baseline: 1.0251x; 1.0251x over previous
#include <cuda_runtime.h>
#include <cuda_bf16.h>

// Problem constants (fixed by the dataset): B=32, L=256, V=50000, C=128
#define CC   128
#define LL   256
#define BDIM 256

typedef unsigned int u32;

// packed bf16x2 helpers (sm_80+ PTX; safe on sm_100a)
__device__ __forceinline__ u32 bf2_fma(u32 a, u32 b, u32 c) {
    u32 d; asm("fma.rn.bf16x2 %0, %1, %2, %3;" : "=r"(d) : "r"(a), "r"(b), "r"(c)); return d;
}
__device__ __forceinline__ u32 bf2_pack(float lo, float hi) {
    // cvt.rn.bf16x2.f32 d, a, b  ->  d.hi = cvt(a), d.lo = cvt(b)
    u32 d; asm("cvt.rn.bf16x2.f32 %0, %1, %2;" : "=r"(d) : "f"(hi), "f"(lo)); return d;
}
__device__ __forceinline__ float bf2_lo(u32 v) { return __uint_as_float(v << 16); }
__device__ __forceinline__ float bf2_hi(u32 v) { return __uint_as_float(v & 0xFFFF0000u); }

__global__ __launch_bounds__(BDIM, 1)
void crf_fwd_kernel(const int*   __restrict__ tokens,
                    const int*   __restrict__ target,
                    const float* __restrict__ mask,
                    const float* __restrict__ st,      // state_table [V, C]
                    const float* __restrict__ trans,   // trans_matrix [C, C]
                    float*       __restrict__ out)     // [B]
{
    // p stored as duplicated bf16x2 {p_i, p_i}, double buffered.
    // Quarter stride = 36 entries (144B): 16B-aligned uint4 reads, and the four
    // quarter-broadcast LDS.128 addresses land on disjoint banks (36 % 32 = 4).
    __shared__ __align__(16) u32 p2_s[2][144];
    __shared__ int   tok_s[LL];
    __shared__ float m_s[LL];
    __shared__ float red_s[8], red2_s[8];

    const int b   = blockIdx.x;
    const int tid = threadIdx.x;
    const int w   = tid >> 5;
    const int l   = tid & 31;
    const int jp  = w * 8 + (l & 7);  // j-pair 0..63 -> states (2jp, 2jp+1)
    const int q   = l >> 3;           // i-quarter 0..3 (32 i's each)

    // ---- stage tokens/mask + target-path energy partial ----
    tok_s[tid] = tokens[b * LL + tid];
    m_s[tid]   = mask[b * LL + tid];
    float tgt_part;
    {
        const int t    = tid;                               // BDIM == LL
        const int tg   = target[b * LL + t];
        const int prev = (t == 0) ? (CC - 1) : target[b * LL + t - 1];
        const int tok  = tokens[b * LL + t];
        tgt_part = (trans[prev * CC + tg] + st[tok * CC + tg]) * mask[b * LL + t];
    }

    // ---- E2[k] = bf16x2{ exp(trans[i][2jp]), exp(trans[i][2jp+1]) }, i = q*32+k ----
    u32 E2[32];
#pragma unroll
    for (int k = 0; k < 32; ++k) {
        const int i = q * 32 + k;
        const float2 tv = *reinterpret_cast<const float2*>(trans + i * CC + 2 * jp);
        E2[k] = bf2_pack(__expf(tv.x), __expf(tv.y));
    }
    __syncthreads();   // tok_s/m_s visible

    // ---- init: p_1[j] = exp((trans[C-1][j] + em_0[j]) * m0) ----
    const float m0 = m_s[0];
    const int   i0 = 2 * jp;
    const int   ei = (i0 >> 5) * 36 + (i0 & 31);   // padded (even) store index
    float p0r, p1r;
    {
        const float2 t127 = *reinterpret_cast<const float2*>(trans + (CC - 1) * CC + i0);
        const float2 e0   = *reinterpret_cast<const float2*>(st + tok_s[0] * CC + i0);
        p0r = __expf((t127.x + e0.x) * m0);
        p1r = __expf((t127.y + e0.y) * m0);
        if (q == 0)
            *reinterpret_cast<uint2*>(&p2_s[0][ei]) =
                make_uint2(bf2_pack(p0r, p0r), bf2_pack(p1r, p1r));
    }
    // emission exp pipeline (q==0 lanes carry real values)
    float ec0 = 1.f, ec1 = 1.f, en0 = 1.f, en1 = 1.f;
    if (q == 0) {
        const float2 e1 = *reinterpret_cast<const float2*>(st + tok_s[1] * CC + i0);
        const float2 e2 = *reinterpret_cast<const float2*>(st + tok_s[2] * CC + i0);
        ec0 = __expf(e1.x); ec1 = __expf(e1.y);
        en0 = __expf(e2.x); en1 = __expf(e2.y);
    }
    float S = 0.0f;    // accumulated shift; true part[j] = log p[j] + S
    __syncthreads();

    // ---- sequential scan: packed bf16x2 matvec, branchless, 1 bar/step ----
    for (int t = 1; t < LL; ++t) {
        const int rb = (t - 1) & 1, wb = t & 1;

        const float p0  = bf2_lo(p2_s[rb][0]);       // normalizer (broadcast LDS)
        const float inv = __fdividef(1.0f, p0);      // overlaps the matvec
        const float mt  = m_s[t];

        // prefetch emission row for step t+2 (clamped; off critical path)
        float2 emr = make_float2(0.f, 0.f);
        const int tpre = (t + 2 < LL) ? (t + 2) : (LL - 1);
        if (q == 0)
            emr = __ldg(reinterpret_cast<const float2*>(st + tok_s[tpre] * CC) + jp);

        // packed matvec: each bf16x2 lane pair accumulates only 8 terms
        const uint4* ap = reinterpret_cast<const uint4*>(&p2_s[rb][q * 36]);
        u32 a0 = 0, a1 = 0, a2 = 0, a3 = 0;
#pragma unroll
        for (int k = 0; k < 8; ++k) {
            const uint4 v = ap[k];
            a0 = bf2_fma(v.x, E2[4 * k + 0], a0);
            a1 = bf2_fma(v.y, E2[4 * k + 1], a1);
            a2 = bf2_fma(v.z, E2[4 * k + 2], a2);
            a3 = bf2_fma(v.w, E2[4 * k + 3], a3);
        }
        // combine sub-sums in fp32 (unpack is ALU-pipe work)
        float slo = (bf2_lo(a0) + bf2_lo(a1)) + (bf2_lo(a2) + bf2_lo(a3));
        float shi = (bf2_hi(a0) + bf2_hi(a1)) + (bf2_hi(a2) + bf2_hi(a3));
        slo += __shfl_xor_sync(0xffffffffu, slo, 8);
        shi += __shfl_xor_sync(0xffffffffu, shi, 8);
        slo += __shfl_xor_sync(0xffffffffu, slo, 16);
        shi += __shfl_xor_sync(0xffffffffu, shi, 16);

        // branchless masked update (identical blend formula to the reference)
        const float pn0 = slo * ec0 * inv;
        const float pn1 = shi * ec1 * inv;
        p0r += (pn0 - p0r) * mt;
        p1r += (pn1 - p1r) * mt;
        if (tid == 0) S += mt * __logf(p0);          // off-path, thread 0 only

        if (q == 0)
            *reinterpret_cast<uint2*>(&p2_s[wb][ei]) =
                make_uint2(bf2_pack(p0r, p0r), bf2_pack(p1r, p1r));

        ec0 = en0; ec1 = en1;
        if (q == 0) { en0 = __expf(emr.x); en1 = __expf(emr.y); }  // off-path
        __syncthreads();
    }

    // ---- epilogue: loss = S + log(sum_j p[j]) - tgt_energy ----
    float c = (q == 0) ? (p0r + p1r) : 0.0f;   // each state counted once
#pragma unroll
    for (int o = 16; o; o >>= 1) c += __shfl_xor_sync(0xffffffffu, c, o);
    float tp = tgt_part;
#pragma unroll
    for (int o = 16; o; o >>= 1) tp += __shfl_xor_sync(0xffffffffu, tp, o);
    if (l == 0) { red_s[w] = c; red2_s[w] = tp; }
    __syncthreads();

    if (tid == 0) {
        float ss = 0.f, ts = 0.f;
#pragma unroll
        for (int i = 0; i < 8; ++i) { ss += red_s[i]; ts += red2_s[i]; }
        out[b] = S + logf(ss) - ts;
    }
}

extern "C" void kernel_launch(void* const* d_in, const int* in_sizes, int n_in,
                              void* d_out, int out_size)
{
    const int*   tokens = (const int*)  d_in[0];
    const int*   target = (const int*)  d_in[1];
    const float* mask   = (const float*)d_in[2];
    const float* st     = (const float*)d_in[3];
    const float* trans  = (const float*)d_in[4];
    float*       out    = (float*)d_out;

    const int B = in_sizes[0] / LL;   // 32
    crf_fwd_kernel<<<B, BDIM>>>(tokens, target, mask, st, trans, out);
}